// round 12
// baseline (speedup 1.0000x reference)
#include <cuda_runtime.h>

// ---------------------------------------------------------------------------
// GraphSAGE 3-layer, fp32. N=50000, E=600000, 128->128->128->40.
//   CSR build per call (proven R7)
//   Layers 1,2: FFMA2 GEMM, R2 data layout, 1024 threads (8 warps/SMSP, TM=4)
//   Layer 3:    FFMA2 GEMM (proven R2 form)
//   Aggregation: fused CSR gather+combine, 4-way MLP (proven R7)
// NOTE: tcgen05 is NOT available in this harness build (compute_103 PTX target).
// ---------------------------------------------------------------------------

#define MAXN 50000
#define MAXE 600000

static __device__ float g_TS [MAXN * 256];
static __device__ float g_H  [MAXN * 128];
static __device__ float g_rdeg[MAXN];
static __device__ int   g_degi[MAXN];
static __device__ int   g_off [MAXN + 1];
static __device__ int   g_cur [MAXN];
static __device__ int   g_esrc[MAXE];
static __device__ int   g_bsum[256];

__device__ __forceinline__ unsigned long long pack2(float x) {
    unsigned long long r;
    asm("mov.b64 %0, {%1, %1};" : "=l"(r) : "f"(x));
    return r;
}
__device__ __forceinline__ void ffma2(unsigned long long& d,
                                      unsigned long long a,
                                      unsigned long long b) {
    asm("fma.rn.f32x2 %0, %1, %2, %0;" : "+l"(d) : "l"(a), "l"(b));
}
union U2F2 { unsigned long long u; float2 f; };

// ---------------------------------------------------------------------------
// CSR build (proven R7)
// ---------------------------------------------------------------------------
__global__ void zero_i(int* p, int n) {
    int i = blockIdx.x * blockDim.x + threadIdx.x;
    if (i < n) p[i] = 0;
}
__global__ void count_deg(const int* __restrict__ dst, int E) {
    int i = blockIdx.x * blockDim.x + threadIdx.x;
    if (i < E) atomicAdd(&g_degi[dst[i]], 1);
}
__global__ void scan_block(const int* __restrict__ in, int* __restrict__ out,
                           int* bsum, int n) {
    int i = blockIdx.x * 256 + threadIdx.x;
    int lane = threadIdx.x & 31, w = threadIdx.x >> 5;
    int v = (i < n) ? in[i] : 0;
    int incl = v;
#pragma unroll
    for (int d = 1; d < 32; d <<= 1) {
        int t = __shfl_up_sync(0xffffffffu, incl, d);
        if (lane >= d) incl += t;
    }
    __shared__ int ws[8];
    if (lane == 31) ws[w] = incl;
    __syncthreads();
    if (threadIdx.x < 8) {
        int x = ws[threadIdx.x];
        int in2 = x;
#pragma unroll
        for (int d = 1; d < 8; d <<= 1) {
            int t = __shfl_up_sync(0xffu, in2, d);
            if (threadIdx.x >= (unsigned)d) in2 += t;
        }
        ws[threadIdx.x] = in2 - x;
        if (threadIdx.x == 7 && bsum) bsum[blockIdx.x] = in2;
    }
    __syncthreads();
    if (i < n) out[i] = ws[w] + incl - v;
}
__global__ void add_off(int M, int E) {
    int i = blockIdx.x * blockDim.x + threadIdx.x;
    if (i < M) {
        int o = g_off[i] + g_bsum[i >> 8];
        g_off[i] = o;
        g_cur[i] = o;
    } else if (i == M) {
        g_off[M] = E;
    }
}
__global__ void scatter_edges(const int* __restrict__ src,
                              const int* __restrict__ dst, int E) {
    int e = blockIdx.x * blockDim.x + threadIdx.x;
    if (e < E) {
        int slot = atomicAdd(&g_cur[dst[e]], 1);
        g_esrc[slot] = src[e];
    }
}
__global__ void make_rdeg(int M) {
    int i = blockIdx.x * blockDim.x + threadIdx.x;
    if (i < M) g_rdeg[i] = 1.0f / fmaxf((float)g_degi[i], 1.0f);
}

// ---------------------------------------------------------------------------
// GEMM 128->256: out[M x 256] = A[M x 128] @ [Wn | Ws]
// R2 smem layout exactly; 1024 threads, 32 warps, TM=4 rows/warp.
// ---------------------------------------------------------------------------
__global__ void __launch_bounds__(1024, 1)
gemm128(const float* __restrict__ A,
        const float* __restrict__ Wn,
        const float* __restrict__ Ws,
        float* __restrict__ out, int M) {
    constexpr int ASTR = 132;
    extern __shared__ float sm[];
    float* Wsh = sm;               // 128 x 256 (R2 layout: row k, col c at k*256+c)
    float* Ash = sm + 128 * 256;   // 128 x ASTR

    const int tid = threadIdx.x;
    const int row0 = blockIdx.x * 128;

    // stage W = [Wn | Ws] (R2 staging)
    for (int i = tid; i < 128 * 32; i += 1024) {
        int k = i >> 5;
        int c = (i & 31) * 4;
        float4 wn = *reinterpret_cast<const float4*>(Wn + k * 128 + c);
        float4 ws = *reinterpret_cast<const float4*>(Ws + k * 128 + c);
        *reinterpret_cast<float4*>(Wsh + k * 256 + c) = wn;
        *reinterpret_cast<float4*>(Wsh + k * 256 + 128 + c) = ws;
    }
    // stage A tile (row-major, padded stride)
    for (int i = tid; i < 128 * 32; i += 1024) {
        int r = i >> 5;
        int kc = (i & 31) * 4;
        int gr = row0 + r;
        if (gr >= M) gr = M - 1;
        float4 a = *reinterpret_cast<const float4*>(A + (size_t)gr * 128 + kc);
        *reinterpret_cast<float4*>(Ash + r * ASTR + kc) = a;
    }
    __syncthreads();

    const int ct = tid & 31;          // lane -> 8 output cols
    const int rt = tid >> 5;          // warp -> 4 rows
    const int colbase = ct * 8;
    const float* arow = Ash + rt * 4 * ASTR;

    unsigned long long acc[4][4];
#pragma unroll
    for (int i = 0; i < 4; i++)
#pragma unroll
        for (int p = 0; p < 4; p++) acc[i][p] = 0ull;

#pragma unroll 4
    for (int k = 0; k < 128; ++k) {
        unsigned long long w[4];
#pragma unroll
        for (int p = 0; p < 4; p++)
            w[p] = *reinterpret_cast<const unsigned long long*>(
                Wsh + k * 256 + colbase + 2 * p);
#pragma unroll
        for (int i = 0; i < 4; i++) {
            unsigned long long aa = pack2(arow[i * ASTR + k]);
#pragma unroll
            for (int p = 0; p < 4; p++) ffma2(acc[i][p], aa, w[p]);
        }
    }

#pragma unroll
    for (int i = 0; i < 4; i++) {
        int gr = row0 + rt * 4 + i;
        if (gr < M) {
            float* o = out + (size_t)gr * 256 + colbase;
#pragma unroll
            for (int p = 0; p < 4; p += 2) {
                U2F2 u0, u1;
                u0.u = acc[i][p];
                u1.u = acc[i][p + 1];
                *reinterpret_cast<float4*>(o + 2 * p) =
                    make_float4(u0.f.x, u0.f.y, u1.f.x, u1.f.y);
            }
        }
    }
}

// ---------------------------------------------------------------------------
// FFMA2 GEMM for layer 3 (proven R2 form)
// ---------------------------------------------------------------------------
template <int DOUT, int CT, int RT, int TM, int TNP>
__global__ void __launch_bounds__(CT * RT, 1)
gemm_fused(const float* __restrict__ A,
           const float* __restrict__ Wn,
           const float* __restrict__ Ws,
           float* __restrict__ out, int M) {
    constexpr int NOUT = 2 * DOUT;
    constexpr int BM = RT * TM;
    constexpr int NT = CT * RT;
    constexpr int ASTR = 132;

    extern __shared__ float smf[];
    float* Wsh = smf;
    float* Ash = smf + 128 * NOUT;

    const int tid = threadIdx.x;
    const int row0 = blockIdx.x * BM;

    for (int i = tid; i < 128 * (DOUT / 4); i += NT) {
        int k = i / (DOUT / 4);
        int c = (i % (DOUT / 4)) * 4;
        float4 wn = *reinterpret_cast<const float4*>(Wn + k * DOUT + c);
        float4 ws = *reinterpret_cast<const float4*>(Ws + k * DOUT + c);
        *reinterpret_cast<float4*>(Wsh + k * NOUT + c) = wn;
        *reinterpret_cast<float4*>(Wsh + k * NOUT + DOUT + c) = ws;
    }
    for (int i = tid; i < BM * 32; i += NT) {
        int r = i / 32;
        int kc = (i % 32) * 4;
        int gr = row0 + r;
        if (gr >= M) gr = M - 1;
        float4 a = *reinterpret_cast<const float4*>(A + (size_t)gr * 128 + kc);
        *reinterpret_cast<float4*>(Ash + r * ASTR + kc) = a;
    }
    __syncthreads();

    const int ct = tid % CT;
    const int rt = tid / CT;
    const int colbase = ct * (TNP * 2);
    const float* arow = Ash + rt * TM * ASTR;

    unsigned long long acc[TM][TNP];
#pragma unroll
    for (int i = 0; i < TM; i++)
#pragma unroll
        for (int p = 0; p < TNP; p++) acc[i][p] = 0ull;

#pragma unroll 4
    for (int k = 0; k < 128; ++k) {
        unsigned long long w[TNP];
#pragma unroll
        for (int p = 0; p < TNP; p++)
            w[p] = *reinterpret_cast<const unsigned long long*>(
                Wsh + k * NOUT + colbase + 2 * p);
#pragma unroll
        for (int i = 0; i < TM; i++) {
            unsigned long long aa = pack2(arow[i * ASTR + k]);
#pragma unroll
            for (int p = 0; p < TNP; p++) ffma2(acc[i][p], aa, w[p]);
        }
    }

#pragma unroll
    for (int i = 0; i < TM; i++) {
        int gr = row0 + rt * TM + i;
        if (gr < M) {
            float* o = out + (size_t)gr * NOUT + colbase;
#pragma unroll
            for (int p = 0; p < TNP; p += 2) {
                U2F2 u0, u1;
                u0.u = acc[i][p];
                u1.u = acc[i][p + 1];
                *reinterpret_cast<float4*>(o + 2 * p) =
                    make_float4(u0.f.x, u0.f.y, u1.f.x, u1.f.y);
            }
        }
    }
}

// ---------------------------------------------------------------------------
// Fused CSR aggregate + combine (proven R7)
// ---------------------------------------------------------------------------
template <bool RELU>
__global__ void aggcomb128(const float* __restrict__ TS,
                           const float* __restrict__ b,
                           float* __restrict__ out, int M) {
    int n = blockIdx.x * 8 + (threadIdx.x >> 5);
    if (n >= M) return;
    int lane = threadIdx.x & 31;
    int beg = g_off[n], end = g_off[n + 1];

    float4 a0 = make_float4(0.f, 0.f, 0.f, 0.f);
    float4 a1 = make_float4(0.f, 0.f, 0.f, 0.f);
    float4 a2 = make_float4(0.f, 0.f, 0.f, 0.f);
    float4 a3 = make_float4(0.f, 0.f, 0.f, 0.f);

    for (int j0 = beg; j0 < end; j0 += 32) {
        int cnt = min(32, end - j0);
        int s = (lane < cnt) ? g_esrc[j0 + lane] : 0;
        int t = 0;
        for (; t + 3 < cnt; t += 4) {
            int s0 = __shfl_sync(0xffffffffu, s, t);
            int s1 = __shfl_sync(0xffffffffu, s, t + 1);
            int s2 = __shfl_sync(0xffffffffu, s, t + 2);
            int s3 = __shfl_sync(0xffffffffu, s, t + 3);
            float4 v0 = *reinterpret_cast<const float4*>(TS + (size_t)s0 * 256 + lane * 4);
            float4 v1 = *reinterpret_cast<const float4*>(TS + (size_t)s1 * 256 + lane * 4);
            float4 v2 = *reinterpret_cast<const float4*>(TS + (size_t)s2 * 256 + lane * 4);
            float4 v3 = *reinterpret_cast<const float4*>(TS + (size_t)s3 * 256 + lane * 4);
            a0.x += v0.x; a0.y += v0.y; a0.z += v0.z; a0.w += v0.w;
            a1.x += v1.x; a1.y += v1.y; a1.z += v1.z; a1.w += v1.w;
            a2.x += v2.x; a2.y += v2.y; a2.z += v2.z; a2.w += v2.w;
            a3.x += v3.x; a3.y += v3.y; a3.z += v3.z; a3.w += v3.w;
        }
        for (; t < cnt; ++t) {
            int s0 = __shfl_sync(0xffffffffu, s, t);
            float4 v0 = *reinterpret_cast<const float4*>(TS + (size_t)s0 * 256 + lane * 4);
            a0.x += v0.x; a0.y += v0.y; a0.z += v0.z; a0.w += v0.w;
        }
    }
    float r = g_rdeg[n];
    float4 sf = *reinterpret_cast<const float4*>(TS + (size_t)n * 256 + 128 + lane * 4);
    float4 bb = *reinterpret_cast<const float4*>(b + lane * 4);
    float4 v;
    v.x = sf.x + (a0.x + a1.x + a2.x + a3.x) * r + bb.x;
    v.y = sf.y + (a0.y + a1.y + a2.y + a3.y) * r + bb.y;
    v.z = sf.z + (a0.z + a1.z + a2.z + a3.z) * r + bb.z;
    v.w = sf.w + (a0.w + a1.w + a2.w + a3.w) * r + bb.w;
    if (RELU) {
        v.x = fmaxf(v.x, 0.f); v.y = fmaxf(v.y, 0.f);
        v.z = fmaxf(v.z, 0.f); v.w = fmaxf(v.w, 0.f);
    }
    *reinterpret_cast<float4*>(out + (size_t)n * 128 + lane * 4) = v;
}

__global__ void aggcomb40(const float* __restrict__ TS,
                          const float* __restrict__ b,
                          float* __restrict__ out, int M) {
    int n = blockIdx.x * 8 + (threadIdx.x >> 5);
    if (n >= M) return;
    int lane = threadIdx.x & 31;
    int beg = g_off[n], end = g_off[n + 1];
    bool act = lane < 10;
    int laneo = act ? lane : 0;

    float4 a0 = make_float4(0.f, 0.f, 0.f, 0.f);
    float4 a1 = make_float4(0.f, 0.f, 0.f, 0.f);
    float4 a2 = make_float4(0.f, 0.f, 0.f, 0.f);
    float4 a3 = make_float4(0.f, 0.f, 0.f, 0.f);

    for (int j0 = beg; j0 < end; j0 += 32) {
        int cnt = min(32, end - j0);
        int s = (lane < cnt) ? g_esrc[j0 + lane] : 0;
        int t = 0;
        for (; t + 3 < cnt; t += 4) {
            int s0 = __shfl_sync(0xffffffffu, s, t);
            int s1 = __shfl_sync(0xffffffffu, s, t + 1);
            int s2 = __shfl_sync(0xffffffffu, s, t + 2);
            int s3 = __shfl_sync(0xffffffffu, s, t + 3);
            float4 v0 = *reinterpret_cast<const float4*>(TS + (size_t)s0 * 80 + laneo * 4);
            float4 v1 = *reinterpret_cast<const float4*>(TS + (size_t)s1 * 80 + laneo * 4);
            float4 v2 = *reinterpret_cast<const float4*>(TS + (size_t)s2 * 80 + laneo * 4);
            float4 v3 = *reinterpret_cast<const float4*>(TS + (size_t)s3 * 80 + laneo * 4);
            a0.x += v0.x; a0.y += v0.y; a0.z += v0.z; a0.w += v0.w;
            a1.x += v1.x; a1.y += v1.y; a1.z += v1.z; a1.w += v1.w;
            a2.x += v2.x; a2.y += v2.y; a2.z += v2.z; a2.w += v2.w;
            a3.x += v3.x; a3.y += v3.y; a3.z += v3.z; a3.w += v3.w;
        }
        for (; t < cnt; ++t) {
            int s0 = __shfl_sync(0xffffffffu, s, t);
            float4 v0 = *reinterpret_cast<const float4*>(TS + (size_t)s0 * 80 + laneo * 4);
            a0.x += v0.x; a0.y += v0.y; a0.z += v0.z; a0.w += v0.w;
        }
    }
    if (act) {
        float r = g_rdeg[n];
        float4 sf = *reinterpret_cast<const float4*>(TS + (size_t)n * 80 + 40 + lane * 4);
        float4 bb = *reinterpret_cast<const float4*>(b + lane * 4);
        float4 v;
        v.x = sf.x + (a0.x + a1.x + a2.x + a3.x) * r + bb.x;
        v.y = sf.y + (a0.y + a1.y + a2.y + a3.y) * r + bb.y;
        v.z = sf.z + (a0.z + a1.z + a2.z + a3.z) * r + bb.z;
        v.w = sf.w + (a0.w + a1.w + a2.w + a3.w) * r + bb.w;
        *reinterpret_cast<float4*>(out + (size_t)n * 40 + lane * 4) = v;
    }
}

// ---------------------------------------------------------------------------
// launch
// ---------------------------------------------------------------------------
static inline int cdiv(int a, int b) { return (a + b - 1) / b; }

extern "C" void kernel_launch(void* const* d_in, const int* in_sizes, int n_in,
                              void* d_out, int out_size) {
    const float* feat = (const float*)d_in[0];
    const int*   src  = (const int*)d_in[1];
    const int*   dst  = (const int*)d_in[2];
    const float* wS0 = (const float*)d_in[3];
    const float* wN0 = (const float*)d_in[4];
    const float* b0  = (const float*)d_in[5];
    const float* wS1 = (const float*)d_in[6];
    const float* wN1 = (const float*)d_in[7];
    const float* b1  = (const float*)d_in[8];
    const float* wS2 = (const float*)d_in[9];
    const float* wN2 = (const float*)d_in[10];
    const float* b2  = (const float*)d_in[11];
    float* out = (float*)d_out;

    const int M = in_sizes[0] / 128;
    const int E = in_sizes[1];

    void *pTS, *pH, *pDegi, *pOff, *pBsum;
    cudaGetSymbolAddress(&pTS, g_TS);
    cudaGetSymbolAddress(&pH, g_H);
    cudaGetSymbolAddress(&pDegi, g_degi);
    cudaGetSymbolAddress(&pOff, g_off);
    cudaGetSymbolAddress(&pBsum, g_bsum);
    float* TS = (float*)pTS;
    float* H = (float*)pH;
    int* degi = (int*)pDegi;
    int* off = (int*)pOff;
    int* bsum = (int*)pBsum;

    constexpr int SMEM_A = (128 * 256 + 128 * 132) * 4;  // 198656 B
    constexpr int SMEM_B = (128 * 80 + 128 * 132) * 4;   // 108544 B
    static bool attr_done = false;
    if (!attr_done) {
        cudaFuncSetAttribute((const void*)gemm128,
                             cudaFuncAttributeMaxDynamicSharedMemorySize, SMEM_A);
        cudaFuncSetAttribute((const void*)gemm_fused<40, 10, 32, 4, 4>,
                             cudaFuncAttributeMaxDynamicSharedMemorySize, SMEM_B);
        attr_done = true;
    }

    const int gemm_blocks = cdiv(M, 128);
    const int nscan = cdiv(M, 256);
    const int node_blocks = cdiv(M, 8);

    // ---- CSR build ----
    zero_i<<<cdiv(M, 256), 256>>>(degi, M);
    count_deg<<<cdiv(E, 256), 256>>>(dst, E);
    scan_block<<<nscan, 256>>>(degi, off, bsum, M);
    scan_block<<<1, 256>>>(bsum, bsum, nullptr, nscan);
    add_off<<<cdiv(M + 1, 256), 256>>>(M, E);
    scatter_edges<<<cdiv(E, 256), 256>>>(src, dst, E);
    make_rdeg<<<cdiv(M, 256), 256>>>(M);

    // ---- layer 1 ----
    gemm128<<<gemm_blocks, 1024, SMEM_A>>>(feat, wN0, wS0, TS, M);
    aggcomb128<true><<<node_blocks, 256>>>(TS, b0, H, M);

    // ---- layer 2 ----
    gemm128<<<gemm_blocks, 1024, SMEM_A>>>(H, wN1, wS1, TS, M);
    aggcomb128<true><<<node_blocks, 256>>>(TS, b1, H, M);

    // ---- layer 3 ----
    gemm_fused<40, 10, 32, 4, 4><<<gemm_blocks, 320, SMEM_B>>>(H, wN2, wS2, TS, M);
    aggcomb40<<<node_blocks, 256>>>(TS, b2, out, M);
}

// round 13
// speedup vs baseline: 1.2790x; 1.2790x over previous
#include <cuda_runtime.h>
#include <cuda_bf16.h>
#include <cstdint>

// ---------------------------------------------------------------------------
// GraphSAGE 3-layer, fp32. N=50000, E=600000, 128->128->128->40.
//   CSR build per call (proven R7)
//   Layers 1,2: mma.sync bf16-split GEMM (hi*hi + lo*hi + hi*lo), HMMA pipe
//   Layer 3:    FFMA2 GEMM (proven R2 form)
//   Aggregation: fused CSR gather+combine, 4-way MLP (proven R7)
// tcgen05 unavailable (compute_103 PTX target); mma.sync/ldmatrix are baseline.
// ---------------------------------------------------------------------------

#define MAXN 50000
#define MAXE 600000

static __device__ float          g_TS [MAXN * 256];
static __device__ float          g_H  [MAXN * 128];
static __device__ float          g_rdeg[MAXN];
static __device__ int            g_degi[MAXN];
static __device__ int            g_off [MAXN + 1];
static __device__ int            g_cur [MAXN];
static __device__ int            g_esrc[MAXE];
static __device__ int            g_bsum[256];
// bf16 Bt images per layer: Bt[n][k] = W[k][n], n in 0..255 ([Wn|Ws]), k 0..127
static __device__ unsigned short g_Bh[2][256 * 128];
static __device__ unsigned short g_Bl[2][256 * 128];

__device__ __forceinline__ unsigned long long pack2(float x) {
    unsigned long long r;
    asm("mov.b64 %0, {%1, %1};" : "=l"(r) : "f"(x));
    return r;
}
__device__ __forceinline__ void ffma2(unsigned long long& d,
                                      unsigned long long a,
                                      unsigned long long b) {
    asm("fma.rn.f32x2 %0, %1, %2, %0;" : "+l"(d) : "l"(a), "l"(b));
}
union U2F2 { unsigned long long u; float2 f; };

__device__ __forceinline__ uint32_t smem_u32(const void* p) {
    uint32_t a;
    asm("{ .reg .u64 t; cvta.to.shared.u64 t, %1; cvt.u32.u64 %0, t; }"
        : "=r"(a) : "l"(p));
    return a;
}
__device__ __forceinline__ unsigned pbf2(float x, float y) {
    unsigned short ux = __bfloat16_as_ushort(__float2bfloat16(x));
    unsigned short uy = __bfloat16_as_ushort(__float2bfloat16(y));
    return (unsigned)ux | ((unsigned)uy << 16);
}
__device__ __forceinline__ void ldsm_x4(uint32_t* d, uint32_t addr) {
    asm volatile("ldmatrix.sync.aligned.m8n8.x4.shared.b16 {%0,%1,%2,%3}, [%4];"
                 : "=r"(d[0]), "=r"(d[1]), "=r"(d[2]), "=r"(d[3]) : "r"(addr));
}
__device__ __forceinline__ void mma_bf16(float* c, const uint32_t* a, const uint32_t* b) {
    asm volatile(
        "mma.sync.aligned.m16n8k16.row.col.f32.bf16.bf16.f32 "
        "{%0,%1,%2,%3}, {%4,%5,%6,%7}, {%8,%9}, {%0,%1,%2,%3};"
        : "+f"(c[0]), "+f"(c[1]), "+f"(c[2]), "+f"(c[3])
        : "r"(a[0]), "r"(a[1]), "r"(a[2]), "r"(a[3]), "r"(b[0]), "r"(b[1]));
}

// ---------------------------------------------------------------------------
// Weight prep: Bt_hi/Bt_lo [256][128] bf16 from Wn (128x128) and Ws (128x128)
// ---------------------------------------------------------------------------
__global__ void w_prep(const float* __restrict__ Wn, const float* __restrict__ Ws,
                       unsigned short* __restrict__ bh, unsigned short* __restrict__ bl) {
    int i = blockIdx.x * 256 + threadIdx.x;
    if (i >= 256 * 64) return;
    int n = i >> 6;
    int kp = (i & 63) * 2;
    float w0, w1;
    if (n < 128) { w0 = Wn[kp * 128 + n]; w1 = Wn[(kp + 1) * 128 + n]; }
    else         { w0 = Ws[kp * 128 + n - 128]; w1 = Ws[(kp + 1) * 128 + n - 128]; }
    __nv_bfloat16 h0 = __float2bfloat16(w0), h1 = __float2bfloat16(w1);
    *reinterpret_cast<unsigned*>(bh + n * 128 + kp) =
        (unsigned)__bfloat16_as_ushort(h0) | ((unsigned)__bfloat16_as_ushort(h1) << 16);
    *reinterpret_cast<unsigned*>(bl + n * 128 + kp) =
        pbf2(w0 - __bfloat162float(h0), w1 - __bfloat162float(h1));
}

// ---------------------------------------------------------------------------
// mma.sync GEMM: out[M x 256] = A[M x 128] @ [Wn|Ws] via bf16 split.
// 512 threads, 16 warps: warp = (wm = w&3 -> 32 rows, wn = w>>2 -> 64 cols).
// smem rows stride 136 bf16 (272 B) -> conflict-free ldmatrix.
// ---------------------------------------------------------------------------
#define BSTR 136
// byte offsets in dynamic smem
#define OFF_AHI 0
#define OFF_ALO 34816
#define OFF_BTH 69632
#define OFF_BTL 139264
#define SMEM_MMA 208896

__global__ void __launch_bounds__(512, 1)
gemm128_mma(const float* __restrict__ A,
            const unsigned short* __restrict__ Bhi,
            const unsigned short* __restrict__ Blo,
            float* __restrict__ out, int M) {
    extern __shared__ char smc[];
    unsigned short* Ahi = reinterpret_cast<unsigned short*>(smc + OFF_AHI);
    unsigned short* Alo = reinterpret_cast<unsigned short*>(smc + OFF_ALO);
    unsigned short* Bth = reinterpret_cast<unsigned short*>(smc + OFF_BTH);
    unsigned short* Btl = reinterpret_cast<unsigned short*>(smc + OFF_BTL);

    const int tid = threadIdx.x;
    const int lane = tid & 31;
    const int w = tid >> 5;
    const int row0 = blockIdx.x * 128;

    // stage A (fp32 -> hi/lo bf16), rows r, k-groups g of 4
    for (int i = tid; i < 128 * 32; i += 512) {
        int r = i >> 5;
        int g = i & 31;
        int gr = row0 + r;
        if (gr >= M) gr = M - 1;
        float4 a = *reinterpret_cast<const float4*>(A + (size_t)gr * 128 + g * 4);
        __nv_bfloat16 hx = __float2bfloat16(a.x), hy = __float2bfloat16(a.y);
        __nv_bfloat16 hz = __float2bfloat16(a.z), hw = __float2bfloat16(a.w);
        uint2 hi, lo;
        hi.x = (unsigned)__bfloat16_as_ushort(hx) | ((unsigned)__bfloat16_as_ushort(hy) << 16);
        hi.y = (unsigned)__bfloat16_as_ushort(hz) | ((unsigned)__bfloat16_as_ushort(hw) << 16);
        lo.x = pbf2(a.x - __bfloat162float(hx), a.y - __bfloat162float(hy));
        lo.y = pbf2(a.z - __bfloat162float(hz), a.w - __bfloat162float(hw));
        *reinterpret_cast<uint2*>(Ahi + r * BSTR + g * 4) = hi;
        *reinterpret_cast<uint2*>(Alo + r * BSTR + g * 4) = lo;
    }
    // stage Bt hi/lo (already bf16 in gmem)
    for (int i = tid; i < 256 * 32; i += 512) {
        int n = i >> 5;
        int g = i & 31;
        uint2 h = *reinterpret_cast<const uint2*>(Bhi + n * 128 + g * 4);
        uint2 l = *reinterpret_cast<const uint2*>(Blo + n * 128 + g * 4);
        *reinterpret_cast<uint2*>(Bth + n * BSTR + g * 4) = h;
        *reinterpret_cast<uint2*>(Btl + n * BSTR + g * 4) = l;
    }
    __syncthreads();

    const int wm = w & 3;        // 32-row group
    const int wn = w >> 2;       // 64-col group
    const int mat = lane >> 3;   // ldmatrix quad
    const int rim = lane & 7;

    float acc[2][8][4];
#pragma unroll
    for (int mt = 0; mt < 2; mt++)
#pragma unroll
        for (int nt = 0; nt < 8; nt++)
#pragma unroll
            for (int q = 0; q < 4; q++) acc[mt][nt][q] = 0.f;

    // A ldmatrix row/k offsets (per lane, mt added in loop)
    const int a_r_base = wm * 32 + (mat & 1) * 8 + rim;
    const int a_k_off = (mat >> 1) * 8;
    // B ldmatrix: n depends on np, k on mat&1
    const int b_n_base = wn * 64 + (mat >> 1) * 8 + rim;
    const int b_k_off = (mat & 1) * 8;

#pragma unroll
    for (int term = 0; term < 3; term++) {
        const unsigned short* As = (term == 1) ? Alo : Ahi;
        const unsigned short* Bs = (term == 2) ? Btl : Bth;
#pragma unroll
        for (int ks = 0; ks < 8; ks++) {
            const int k0 = ks * 16;
            uint32_t afr[2][4];
#pragma unroll
            for (int mt = 0; mt < 2; mt++) {
                uint32_t addr = smem_u32(As + (a_r_base + mt * 16) * BSTR + k0 + a_k_off);
                ldsm_x4(afr[mt], addr);
            }
#pragma unroll
            for (int np = 0; np < 4; np++) {
                uint32_t bfr[4];
                uint32_t addr = smem_u32(Bs + (b_n_base + np * 16) * BSTR + k0 + b_k_off);
                ldsm_x4(bfr, addr);
                mma_bf16(acc[0][2 * np],     afr[0], bfr);
                mma_bf16(acc[0][2 * np + 1], afr[0], bfr + 2);
                mma_bf16(acc[1][2 * np],     afr[1], bfr);
                mma_bf16(acc[1][2 * np + 1], afr[1], bfr + 2);
            }
        }
    }

    // epilogue: c0,c1 -> (row gid, cols 2tig,2tig+1); c2,c3 -> row gid+8
    const int gid = lane >> 2;
    const int tig = lane & 3;
#pragma unroll
    for (int mt = 0; mt < 2; mt++) {
#pragma unroll
        for (int half = 0; half < 2; half++) {
            int r = row0 + wm * 32 + mt * 16 + half * 8 + gid;
            if (r < M) {
                float* o = out + (size_t)r * 256 + wn * 64 + tig * 2;
#pragma unroll
                for (int nt = 0; nt < 8; nt++) {
                    float2 v = make_float2(acc[mt][nt][2 * half], acc[mt][nt][2 * half + 1]);
                    *reinterpret_cast<float2*>(o + nt * 8) = v;
                }
            }
        }
    }
}

// ---------------------------------------------------------------------------
// CSR build (proven R7)
// ---------------------------------------------------------------------------
__global__ void zero_i(int* p, int n) {
    int i = blockIdx.x * blockDim.x + threadIdx.x;
    if (i < n) p[i] = 0;
}
__global__ void count_deg(const int* __restrict__ dst, int E) {
    int i = blockIdx.x * blockDim.x + threadIdx.x;
    if (i < E) atomicAdd(&g_degi[dst[i]], 1);
}
__global__ void scan_block(const int* __restrict__ in, int* __restrict__ out,
                           int* bsum, int n) {
    int i = blockIdx.x * 256 + threadIdx.x;
    int lane = threadIdx.x & 31, w = threadIdx.x >> 5;
    int v = (i < n) ? in[i] : 0;
    int incl = v;
#pragma unroll
    for (int d = 1; d < 32; d <<= 1) {
        int t = __shfl_up_sync(0xffffffffu, incl, d);
        if (lane >= d) incl += t;
    }
    __shared__ int ws[8];
    if (lane == 31) ws[w] = incl;
    __syncthreads();
    if (threadIdx.x < 8) {
        int x = ws[threadIdx.x];
        int in2 = x;
#pragma unroll
        for (int d = 1; d < 8; d <<= 1) {
            int t = __shfl_up_sync(0xffu, in2, d);
            if (threadIdx.x >= (unsigned)d) in2 += t;
        }
        ws[threadIdx.x] = in2 - x;
        if (threadIdx.x == 7 && bsum) bsum[blockIdx.x] = in2;
    }
    __syncthreads();
    if (i < n) out[i] = ws[w] + incl - v;
}
__global__ void add_off(int M, int E) {
    int i = blockIdx.x * blockDim.x + threadIdx.x;
    if (i < M) {
        int o = g_off[i] + g_bsum[i >> 8];
        g_off[i] = o;
        g_cur[i] = o;
    } else if (i == M) {
        g_off[M] = E;
    }
}
__global__ void scatter_edges(const int* __restrict__ src,
                              const int* __restrict__ dst, int E) {
    int e = blockIdx.x * blockDim.x + threadIdx.x;
    if (e < E) {
        int slot = atomicAdd(&g_cur[dst[e]], 1);
        g_esrc[slot] = src[e];
    }
}
__global__ void make_rdeg(int M) {
    int i = blockIdx.x * blockDim.x + threadIdx.x;
    if (i < M) g_rdeg[i] = 1.0f / fmaxf((float)g_degi[i], 1.0f);
}

// ---------------------------------------------------------------------------
// FFMA2 GEMM for layer 3 (proven R2 form)
// ---------------------------------------------------------------------------
template <int DOUT, int CT, int RT, int TM, int TNP>
__global__ void __launch_bounds__(CT * RT, 1)
gemm_fused(const float* __restrict__ A,
           const float* __restrict__ Wn,
           const float* __restrict__ Ws,
           float* __restrict__ out, int M) {
    constexpr int NOUT = 2 * DOUT;
    constexpr int BM = RT * TM;
    constexpr int NT = CT * RT;
    constexpr int ASTR = 132;

    extern __shared__ float smf[];
    float* Wsh = smf;
    float* Ash = smf + 128 * NOUT;

    const int tid = threadIdx.x;
    const int row0 = blockIdx.x * BM;

    for (int i = tid; i < 128 * (DOUT / 4); i += NT) {
        int k = i / (DOUT / 4);
        int c = (i % (DOUT / 4)) * 4;
        float4 wn = *reinterpret_cast<const float4*>(Wn + k * DOUT + c);
        float4 ws = *reinterpret_cast<const float4*>(Ws + k * DOUT + c);
        *reinterpret_cast<float4*>(Wsh + k * NOUT + c) = wn;
        *reinterpret_cast<float4*>(Wsh + k * NOUT + DOUT + c) = ws;
    }
    for (int i = tid; i < BM * 32; i += NT) {
        int r = i / 32;
        int kc = (i % 32) * 4;
        int gr = row0 + r;
        if (gr >= M) gr = M - 1;
        float4 a = *reinterpret_cast<const float4*>(A + (size_t)gr * 128 + kc);
        *reinterpret_cast<float4*>(Ash + r * ASTR + kc) = a;
    }
    __syncthreads();

    const int ct = tid % CT;
    const int rt = tid / CT;
    const int colbase = ct * (TNP * 2);
    const float* arow = Ash + rt * TM * ASTR;

    unsigned long long acc[TM][TNP];
#pragma unroll
    for (int i = 0; i < TM; i++)
#pragma unroll
        for (int p = 0; p < TNP; p++) acc[i][p] = 0ull;

#pragma unroll 4
    for (int k = 0; k < 128; ++k) {
        unsigned long long w[TNP];
#pragma unroll
        for (int p = 0; p < TNP; p++)
            w[p] = *reinterpret_cast<const unsigned long long*>(
                Wsh + k * NOUT + colbase + 2 * p);
#pragma unroll
        for (int i = 0; i < TM; i++) {
            unsigned long long aa = pack2(arow[i * ASTR + k]);
#pragma unroll
            for (int p = 0; p < TNP; p++) ffma2(acc[i][p], aa, w[p]);
        }
    }

#pragma unroll
    for (int i = 0; i < TM; i++) {
        int gr = row0 + rt * TM + i;
        if (gr < M) {
            float* o = out + (size_t)gr * NOUT + colbase;
#pragma unroll
            for (int p = 0; p < TNP; p += 2) {
                U2F2 u0, u1;
                u0.u = acc[i][p];
                u1.u = acc[i][p + 1];
                *reinterpret_cast<float4*>(o + 2 * p) =
                    make_float4(u0.f.x, u0.f.y, u1.f.x, u1.f.y);
            }
        }
    }
}

// ---------------------------------------------------------------------------
// Fused CSR aggregate + combine (proven R7)
// ---------------------------------------------------------------------------
template <bool RELU>
__global__ void aggcomb128(const float* __restrict__ TS,
                           const float* __restrict__ b,
                           float* __restrict__ out, int M) {
    int n = blockIdx.x * 8 + (threadIdx.x >> 5);
    if (n >= M) return;
    int lane = threadIdx.x & 31;
    int beg = g_off[n], end = g_off[n + 1];

    float4 a0 = make_float4(0.f, 0.f, 0.f, 0.f);
    float4 a1 = make_float4(0.f, 0.f, 0.f, 0.f);
    float4 a2 = make_float4(0.f, 0.f, 0.f, 0.f);
    float4 a3 = make_float4(0.f, 0.f, 0.f, 0.f);

    for (int j0 = beg; j0 < end; j0 += 32) {
        int cnt = min(32, end - j0);
        int s = (lane < cnt) ? g_esrc[j0 + lane] : 0;
        int t = 0;
        for (; t + 3 < cnt; t += 4) {
            int s0 = __shfl_sync(0xffffffffu, s, t);
            int s1 = __shfl_sync(0xffffffffu, s, t + 1);
            int s2 = __shfl_sync(0xffffffffu, s, t + 2);
            int s3 = __shfl_sync(0xffffffffu, s, t + 3);
            float4 v0 = *reinterpret_cast<const float4*>(TS + (size_t)s0 * 256 + lane * 4);
            float4 v1 = *reinterpret_cast<const float4*>(TS + (size_t)s1 * 256 + lane * 4);
            float4 v2 = *reinterpret_cast<const float4*>(TS + (size_t)s2 * 256 + lane * 4);
            float4 v3 = *reinterpret_cast<const float4*>(TS + (size_t)s3 * 256 + lane * 4);
            a0.x += v0.x; a0.y += v0.y; a0.z += v0.z; a0.w += v0.w;
            a1.x += v1.x; a1.y += v1.y; a1.z += v1.z; a1.w += v1.w;
            a2.x += v2.x; a2.y += v2.y; a2.z += v2.z; a2.w += v2.w;
            a3.x += v3.x; a3.y += v3.y; a3.z += v3.z; a3.w += v3.w;
        }
        for (; t < cnt; ++t) {
            int s0 = __shfl_sync(0xffffffffu, s, t);
            float4 v0 = *reinterpret_cast<const float4*>(TS + (size_t)s0 * 256 + lane * 4);
            a0.x += v0.x; a0.y += v0.y; a0.z += v0.z; a0.w += v0.w;
        }
    }
    float r = g_rdeg[n];
    float4 sf = *reinterpret_cast<const float4*>(TS + (size_t)n * 256 + 128 + lane * 4);
    float4 bb = *reinterpret_cast<const float4*>(b + lane * 4);
    float4 v;
    v.x = sf.x + (a0.x + a1.x + a2.x + a3.x) * r + bb.x;
    v.y = sf.y + (a0.y + a1.y + a2.y + a3.y) * r + bb.y;
    v.z = sf.z + (a0.z + a1.z + a2.z + a3.z) * r + bb.z;
    v.w = sf.w + (a0.w + a1.w + a2.w + a3.w) * r + bb.w;
    if (RELU) {
        v.x = fmaxf(v.x, 0.f); v.y = fmaxf(v.y, 0.f);
        v.z = fmaxf(v.z, 0.f); v.w = fmaxf(v.w, 0.f);
    }
    *reinterpret_cast<float4*>(out + (size_t)n * 128 + lane * 4) = v;
}

__global__ void aggcomb40(const float* __restrict__ TS,
                          const float* __restrict__ b,
                          float* __restrict__ out, int M) {
    int n = blockIdx.x * 8 + (threadIdx.x >> 5);
    if (n >= M) return;
    int lane = threadIdx.x & 31;
    int beg = g_off[n], end = g_off[n + 1];
    bool act = lane < 10;
    int laneo = act ? lane : 0;

    float4 a0 = make_float4(0.f, 0.f, 0.f, 0.f);
    float4 a1 = make_float4(0.f, 0.f, 0.f, 0.f);
    float4 a2 = make_float4(0.f, 0.f, 0.f, 0.f);
    float4 a3 = make_float4(0.f, 0.f, 0.f, 0.f);

    for (int j0 = beg; j0 < end; j0 += 32) {
        int cnt = min(32, end - j0);
        int s = (lane < cnt) ? g_esrc[j0 + lane] : 0;
        int t = 0;
        for (; t + 3 < cnt; t += 4) {
            int s0 = __shfl_sync(0xffffffffu, s, t);
            int s1 = __shfl_sync(0xffffffffu, s, t + 1);
            int s2 = __shfl_sync(0xffffffffu, s, t + 2);
            int s3 = __shfl_sync(0xffffffffu, s, t + 3);
            float4 v0 = *reinterpret_cast<const float4*>(TS + (size_t)s0 * 80 + laneo * 4);
            float4 v1 = *reinterpret_cast<const float4*>(TS + (size_t)s1 * 80 + laneo * 4);
            float4 v2 = *reinterpret_cast<const float4*>(TS + (size_t)s2 * 80 + laneo * 4);
            float4 v3 = *reinterpret_cast<const float4*>(TS + (size_t)s3 * 80 + laneo * 4);
            a0.x += v0.x; a0.y += v0.y; a0.z += v0.z; a0.w += v0.w;
            a1.x += v1.x; a1.y += v1.y; a1.z += v1.z; a1.w += v1.w;
            a2.x += v2.x; a2.y += v2.y; a2.z += v2.z; a2.w += v2.w;
            a3.x += v3.x; a3.y += v3.y; a3.z += v3.z; a3.w += v3.w;
        }
        for (; t < cnt; ++t) {
            int s0 = __shfl_sync(0xffffffffu, s, t);
            float4 v0 = *reinterpret_cast<const float4*>(TS + (size_t)s0 * 80 + laneo * 4);
            a0.x += v0.x; a0.y += v0.y; a0.z += v0.z; a0.w += v0.w;
        }
    }
    if (act) {
        float r = g_rdeg[n];
        float4 sf = *reinterpret_cast<const float4*>(TS + (size_t)n * 80 + 40 + lane * 4);
        float4 bb = *reinterpret_cast<const float4*>(b + lane * 4);
        float4 v;
        v.x = sf.x + (a0.x + a1.x + a2.x + a3.x) * r + bb.x;
        v.y = sf.y + (a0.y + a1.y + a2.y + a3.y) * r + bb.y;
        v.z = sf.z + (a0.z + a1.z + a2.z + a3.z) * r + bb.z;
        v.w = sf.w + (a0.w + a1.w + a2.w + a3.w) * r + bb.w;
        *reinterpret_cast<float4*>(out + (size_t)n * 40 + lane * 4) = v;
    }
}

// ---------------------------------------------------------------------------
// launch
// ---------------------------------------------------------------------------
static inline int cdiv(int a, int b) { return (a + b - 1) / b; }

extern "C" void kernel_launch(void* const* d_in, const int* in_sizes, int n_in,
                              void* d_out, int out_size) {
    const float* feat = (const float*)d_in[0];
    const int*   src  = (const int*)d_in[1];
    const int*   dst  = (const int*)d_in[2];
    const float* wS0 = (const float*)d_in[3];
    const float* wN0 = (const float*)d_in[4];
    const float* b0  = (const float*)d_in[5];
    const float* wS1 = (const float*)d_in[6];
    const float* wN1 = (const float*)d_in[7];
    const float* b1  = (const float*)d_in[8];
    const float* wS2 = (const float*)d_in[9];
    const float* wN2 = (const float*)d_in[10];
    const float* b2  = (const float*)d_in[11];
    float* out = (float*)d_out;

    const int M = in_sizes[0] / 128;
    const int E = in_sizes[1];

    void *pTS, *pH, *pDegi, *pOff, *pBsum, *pBh, *pBl;
    cudaGetSymbolAddress(&pTS, g_TS);
    cudaGetSymbolAddress(&pH, g_H);
    cudaGetSymbolAddress(&pDegi, g_degi);
    cudaGetSymbolAddress(&pOff, g_off);
    cudaGetSymbolAddress(&pBsum, g_bsum);
    cudaGetSymbolAddress(&pBh, g_Bh);
    cudaGetSymbolAddress(&pBl, g_Bl);
    float* TS = (float*)pTS;
    float* H = (float*)pH;
    int* degi = (int*)pDegi;
    int* off = (int*)pOff;
    int* bsum = (int*)pBsum;
    unsigned short* Bh = (unsigned short*)pBh;  // [2][256*128]
    unsigned short* Bl = (unsigned short*)pBl;

    constexpr int SMEM_B = (128 * 80 + 128 * 132) * 4;   // 108544 B
    static bool attr_done = false;
    if (!attr_done) {
        cudaFuncSetAttribute((const void*)gemm128_mma,
                             cudaFuncAttributeMaxDynamicSharedMemorySize, SMEM_MMA);
        cudaFuncSetAttribute((const void*)gemm_fused<40, 10, 32, 4, 4>,
                             cudaFuncAttributeMaxDynamicSharedMemorySize, SMEM_B);
        attr_done = true;
    }

    const int gemm_blocks = cdiv(M, 128);
    const int nscan = cdiv(M, 256);
    const int node_blocks = cdiv(M, 8);

    // ---- weight prep ----
    w_prep<<<64, 256>>>(wN0, wS0, Bh + 0 * 32768, Bl + 0 * 32768);
    w_prep<<<64, 256>>>(wN1, wS1, Bh + 1 * 32768, Bl + 1 * 32768);

    // ---- CSR build ----
    zero_i<<<cdiv(M, 256), 256>>>(degi, M);
    count_deg<<<cdiv(E, 256), 256>>>(dst, E);
    scan_block<<<nscan, 256>>>(degi, off, bsum, M);
    scan_block<<<1, 256>>>(bsum, bsum, nullptr, nscan);
    add_off<<<cdiv(M + 1, 256), 256>>>(M, E);
    scatter_edges<<<cdiv(E, 256), 256>>>(src, dst, E);
    make_rdeg<<<cdiv(M, 256), 256>>>(M);

    // ---- layer 1 ----
    gemm128_mma<<<gemm_blocks, 512, SMEM_MMA>>>(feat, Bh, Bl, TS, M);
    aggcomb128<true><<<node_blocks, 256>>>(TS, b0, H, M);

    // ---- layer 2 ----
    gemm128_mma<<<gemm_blocks, 512, SMEM_MMA>>>(H, Bh + 32768, Bl + 32768, TS, M);
    aggcomb128<true><<<node_blocks, 256>>>(TS, b1, H, M);

    // ---- layer 3 ----
    gemm_fused<40, 10, 32, 4, 4><<<gemm_blocks, 320, SMEM_B>>>(H, wN2, wS2, TS, M);
    aggcomb40<<<node_blocks, 256>>>(TS, b2, out, M);
}

// round 14
// speedup vs baseline: 1.3103x; 1.0244x over previous
#include <cuda_runtime.h>
#include <cuda_bf16.h>
#include <cstdint>

// ---------------------------------------------------------------------------
// GraphSAGE 3-layer, fp32. N=50000, E=600000, 128->128->128->40.
//   Layers 1,2: mma.sync bf16-split GEMM (proven R13, ~FFMA-rate on sm_103)
//   Layer 3:    FFMA2 GEMM (proven R2 form)
//   Aggregation: fused CSR gather+combine, 8-way MLP
//   CSR build: vectorized (4 edges/thread), rdeg folded into add_off
// tcgen05 unavailable (compute_103 PTX target). Launch #4 = gemm128_mma (profiled).
// ---------------------------------------------------------------------------

#define MAXN 50000
#define MAXE 600000

static __device__ float          g_TS [MAXN * 256];
static __device__ float          g_H  [MAXN * 128];
static __device__ float          g_rdeg[MAXN];
static __device__ int            g_degi[MAXN];
static __device__ int            g_off [MAXN + 1];
static __device__ int            g_cur [MAXN];
static __device__ int            g_esrc[MAXE];
static __device__ int            g_bsum[256];
static __device__ unsigned short g_Bh[2][256 * 128];
static __device__ unsigned short g_Bl[2][256 * 128];

__device__ __forceinline__ unsigned long long pack2(float x) {
    unsigned long long r;
    asm("mov.b64 %0, {%1, %1};" : "=l"(r) : "f"(x));
    return r;
}
__device__ __forceinline__ void ffma2(unsigned long long& d,
                                      unsigned long long a,
                                      unsigned long long b) {
    asm("fma.rn.f32x2 %0, %1, %2, %0;" : "+l"(d) : "l"(a), "l"(b));
}
union U2F2 { unsigned long long u; float2 f; };

__device__ __forceinline__ uint32_t smem_u32(const void* p) {
    uint32_t a;
    asm("{ .reg .u64 t; cvta.to.shared.u64 t, %1; cvt.u32.u64 %0, t; }"
        : "=r"(a) : "l"(p));
    return a;
}
__device__ __forceinline__ unsigned pbf2(float x, float y) {
    unsigned short ux = __bfloat16_as_ushort(__float2bfloat16(x));
    unsigned short uy = __bfloat16_as_ushort(__float2bfloat16(y));
    return (unsigned)ux | ((unsigned)uy << 16);
}
__device__ __forceinline__ void ldsm_x4(uint32_t* d, uint32_t addr) {
    asm volatile("ldmatrix.sync.aligned.m8n8.x4.shared.b16 {%0,%1,%2,%3}, [%4];"
                 : "=r"(d[0]), "=r"(d[1]), "=r"(d[2]), "=r"(d[3]) : "r"(addr));
}
__device__ __forceinline__ void mma_bf16(float* c, const uint32_t* a, const uint32_t* b) {
    asm volatile(
        "mma.sync.aligned.m16n8k16.row.col.f32.bf16.bf16.f32 "
        "{%0,%1,%2,%3}, {%4,%5,%6,%7}, {%8,%9}, {%0,%1,%2,%3};"
        : "+f"(c[0]), "+f"(c[1]), "+f"(c[2]), "+f"(c[3])
        : "r"(a[0]), "r"(a[1]), "r"(a[2]), "r"(a[3]), "r"(b[0]), "r"(b[1]));
}

// ---------------------------------------------------------------------------
// Weight prep (proven R13)
// ---------------------------------------------------------------------------
__global__ void w_prep(const float* __restrict__ Wn, const float* __restrict__ Ws,
                       unsigned short* __restrict__ bh, unsigned short* __restrict__ bl) {
    int i = blockIdx.x * 256 + threadIdx.x;
    if (i >= 256 * 64) return;
    int n = i >> 6;
    int kp = (i & 63) * 2;
    float w0, w1;
    if (n < 128) { w0 = Wn[kp * 128 + n]; w1 = Wn[(kp + 1) * 128 + n]; }
    else         { w0 = Ws[kp * 128 + n - 128]; w1 = Ws[(kp + 1) * 128 + n - 128]; }
    __nv_bfloat16 h0 = __float2bfloat16(w0), h1 = __float2bfloat16(w1);
    *reinterpret_cast<unsigned*>(bh + n * 128 + kp) =
        (unsigned)__bfloat16_as_ushort(h0) | ((unsigned)__bfloat16_as_ushort(h1) << 16);
    *reinterpret_cast<unsigned*>(bl + n * 128 + kp) =
        pbf2(w0 - __bfloat162float(h0), w1 - __bfloat162float(h1));
}

// ---------------------------------------------------------------------------
// mma.sync GEMM (proven R13, unchanged)
// ---------------------------------------------------------------------------
#define BSTR 136
#define OFF_AHI 0
#define OFF_ALO 34816
#define OFF_BTH 69632
#define OFF_BTL 139264
#define SMEM_MMA 208896

__global__ void __launch_bounds__(512, 1)
gemm128_mma(const float* __restrict__ A,
            const unsigned short* __restrict__ Bhi,
            const unsigned short* __restrict__ Blo,
            float* __restrict__ out, int M) {
    extern __shared__ char smc[];
    unsigned short* Ahi = reinterpret_cast<unsigned short*>(smc + OFF_AHI);
    unsigned short* Alo = reinterpret_cast<unsigned short*>(smc + OFF_ALO);
    unsigned short* Bth = reinterpret_cast<unsigned short*>(smc + OFF_BTH);
    unsigned short* Btl = reinterpret_cast<unsigned short*>(smc + OFF_BTL);

    const int tid = threadIdx.x;
    const int lane = tid & 31;
    const int w = tid >> 5;
    const int row0 = blockIdx.x * 128;

    for (int i = tid; i < 128 * 32; i += 512) {
        int r = i >> 5;
        int g = i & 31;
        int gr = row0 + r;
        if (gr >= M) gr = M - 1;
        float4 a = *reinterpret_cast<const float4*>(A + (size_t)gr * 128 + g * 4);
        __nv_bfloat16 hx = __float2bfloat16(a.x), hy = __float2bfloat16(a.y);
        __nv_bfloat16 hz = __float2bfloat16(a.z), hw = __float2bfloat16(a.w);
        uint2 hi, lo;
        hi.x = (unsigned)__bfloat16_as_ushort(hx) | ((unsigned)__bfloat16_as_ushort(hy) << 16);
        hi.y = (unsigned)__bfloat16_as_ushort(hz) | ((unsigned)__bfloat16_as_ushort(hw) << 16);
        lo.x = pbf2(a.x - __bfloat162float(hx), a.y - __bfloat162float(hy));
        lo.y = pbf2(a.z - __bfloat162float(hz), a.w - __bfloat162float(hw));
        *reinterpret_cast<uint2*>(Ahi + r * BSTR + g * 4) = hi;
        *reinterpret_cast<uint2*>(Alo + r * BSTR + g * 4) = lo;
    }
    for (int i = tid; i < 256 * 32; i += 512) {
        int n = i >> 5;
        int g = i & 31;
        uint2 h = *reinterpret_cast<const uint2*>(Bhi + n * 128 + g * 4);
        uint2 l = *reinterpret_cast<const uint2*>(Blo + n * 128 + g * 4);
        *reinterpret_cast<uint2*>(Bth + n * BSTR + g * 4) = h;
        *reinterpret_cast<uint2*>(Btl + n * BSTR + g * 4) = l;
    }
    __syncthreads();

    const int wm = w & 3;
    const int wn = w >> 2;
    const int mat = lane >> 3;
    const int rim = lane & 7;

    float acc[2][8][4];
#pragma unroll
    for (int mt = 0; mt < 2; mt++)
#pragma unroll
        for (int nt = 0; nt < 8; nt++)
#pragma unroll
            for (int q = 0; q < 4; q++) acc[mt][nt][q] = 0.f;

    const int a_r_base = wm * 32 + (mat & 1) * 8 + rim;
    const int a_k_off = (mat >> 1) * 8;
    const int b_n_base = wn * 64 + (mat >> 1) * 8 + rim;
    const int b_k_off = (mat & 1) * 8;

#pragma unroll
    for (int term = 0; term < 3; term++) {
        const unsigned short* As = (term == 1) ? Alo : Ahi;
        const unsigned short* Bs = (term == 2) ? Btl : Bth;
#pragma unroll
        for (int ks = 0; ks < 8; ks++) {
            const int k0 = ks * 16;
            uint32_t afr[2][4];
#pragma unroll
            for (int mt = 0; mt < 2; mt++) {
                uint32_t addr = smem_u32(As + (a_r_base + mt * 16) * BSTR + k0 + a_k_off);
                ldsm_x4(afr[mt], addr);
            }
#pragma unroll
            for (int np = 0; np < 4; np++) {
                uint32_t bfr[4];
                uint32_t addr = smem_u32(Bs + (b_n_base + np * 16) * BSTR + k0 + b_k_off);
                ldsm_x4(bfr, addr);
                mma_bf16(acc[0][2 * np],     afr[0], bfr);
                mma_bf16(acc[0][2 * np + 1], afr[0], bfr + 2);
                mma_bf16(acc[1][2 * np],     afr[1], bfr);
                mma_bf16(acc[1][2 * np + 1], afr[1], bfr + 2);
            }
        }
    }

    const int gid = lane >> 2;
    const int tig = lane & 3;
#pragma unroll
    for (int mt = 0; mt < 2; mt++) {
#pragma unroll
        for (int half = 0; half < 2; half++) {
            int r = row0 + wm * 32 + mt * 16 + half * 8 + gid;
            if (r < M) {
                float* o = out + (size_t)r * 256 + wn * 64 + tig * 2;
#pragma unroll
                for (int nt = 0; nt < 8; nt++) {
                    float2 v = make_float2(acc[mt][nt][2 * half], acc[mt][nt][2 * half + 1]);
                    *reinterpret_cast<float2*>(o + nt * 8) = v;
                }
            }
        }
    }
}

// ---------------------------------------------------------------------------
// CSR build — vectorized 4 edges/thread
// ---------------------------------------------------------------------------
__global__ void zero_i(int* p, int n) {
    int i = blockIdx.x * blockDim.x + threadIdx.x;
    if (i < n) p[i] = 0;
}
__global__ void count_deg4(const int* __restrict__ dst, int E) {
    int i = blockIdx.x * blockDim.x + threadIdx.x;
    int e0 = i * 4;
    if (e0 + 3 < E) {
        int4 d = *reinterpret_cast<const int4*>(dst + e0);
        atomicAdd(&g_degi[d.x], 1);
        atomicAdd(&g_degi[d.y], 1);
        atomicAdd(&g_degi[d.z], 1);
        atomicAdd(&g_degi[d.w], 1);
    } else {
        for (int e = e0; e < E; ++e) atomicAdd(&g_degi[dst[e]], 1);
    }
}
__global__ void scan_block(const int* __restrict__ in, int* __restrict__ out,
                           int* bsum, int n) {
    int i = blockIdx.x * 256 + threadIdx.x;
    int lane = threadIdx.x & 31, w = threadIdx.x >> 5;
    int v = (i < n) ? in[i] : 0;
    int incl = v;
#pragma unroll
    for (int d = 1; d < 32; d <<= 1) {
        int t = __shfl_up_sync(0xffffffffu, incl, d);
        if (lane >= d) incl += t;
    }
    __shared__ int ws[8];
    if (lane == 31) ws[w] = incl;
    __syncthreads();
    if (threadIdx.x < 8) {
        int x = ws[threadIdx.x];
        int in2 = x;
#pragma unroll
        for (int d = 1; d < 8; d <<= 1) {
            int t = __shfl_up_sync(0xffu, in2, d);
            if (threadIdx.x >= (unsigned)d) in2 += t;
        }
        ws[threadIdx.x] = in2 - x;
        if (threadIdx.x == 7 && bsum) bsum[blockIdx.x] = in2;
    }
    __syncthreads();
    if (i < n) out[i] = ws[w] + incl - v;
}
// add block offsets; also produce cursor and rdeg (fused)
__global__ void add_off(int M, int E) {
    int i = blockIdx.x * blockDim.x + threadIdx.x;
    if (i < M) {
        int o = g_off[i] + g_bsum[i >> 8];
        g_off[i] = o;
        g_cur[i] = o;
        g_rdeg[i] = 1.0f / fmaxf((float)g_degi[i], 1.0f);
    } else if (i == M) {
        g_off[M] = E;
    }
}
__global__ void scatter_edges4(const int* __restrict__ src,
                               const int* __restrict__ dst, int E) {
    int i = blockIdx.x * blockDim.x + threadIdx.x;
    int e0 = i * 4;
    if (e0 + 3 < E) {
        int4 d = *reinterpret_cast<const int4*>(dst + e0);
        int4 s = *reinterpret_cast<const int4*>(src + e0);
        g_esrc[atomicAdd(&g_cur[d.x], 1)] = s.x;
        g_esrc[atomicAdd(&g_cur[d.y], 1)] = s.y;
        g_esrc[atomicAdd(&g_cur[d.z], 1)] = s.z;
        g_esrc[atomicAdd(&g_cur[d.w], 1)] = s.w;
    } else {
        for (int e = e0; e < E; ++e)
            g_esrc[atomicAdd(&g_cur[dst[e]], 1)] = src[e];
    }
}

// ---------------------------------------------------------------------------
// FFMA2 GEMM for layer 3 (proven R2 form)
// ---------------------------------------------------------------------------
template <int DOUT, int CT, int RT, int TM, int TNP>
__global__ void __launch_bounds__(CT * RT, 1)
gemm_fused(const float* __restrict__ A,
           const float* __restrict__ Wn,
           const float* __restrict__ Ws,
           float* __restrict__ out, int M) {
    constexpr int NOUT = 2 * DOUT;
    constexpr int BM = RT * TM;
    constexpr int NT = CT * RT;
    constexpr int ASTR = 132;

    extern __shared__ float smf[];
    float* Wsh = smf;
    float* Ash = smf + 128 * NOUT;

    const int tid = threadIdx.x;
    const int row0 = blockIdx.x * BM;

    for (int i = tid; i < 128 * (DOUT / 4); i += NT) {
        int k = i / (DOUT / 4);
        int c = (i % (DOUT / 4)) * 4;
        float4 wn = *reinterpret_cast<const float4*>(Wn + k * DOUT + c);
        float4 ws = *reinterpret_cast<const float4*>(Ws + k * DOUT + c);
        *reinterpret_cast<float4*>(Wsh + k * NOUT + c) = wn;
        *reinterpret_cast<float4*>(Wsh + k * NOUT + DOUT + c) = ws;
    }
    for (int i = tid; i < BM * 32; i += NT) {
        int r = i / 32;
        int kc = (i % 32) * 4;
        int gr = row0 + r;
        if (gr >= M) gr = M - 1;
        float4 a = *reinterpret_cast<const float4*>(A + (size_t)gr * 128 + kc);
        *reinterpret_cast<float4*>(Ash + r * ASTR + kc) = a;
    }
    __syncthreads();

    const int ct = tid % CT;
    const int rt = tid / CT;
    const int colbase = ct * (TNP * 2);
    const float* arow = Ash + rt * TM * ASTR;

    unsigned long long acc[TM][TNP];
#pragma unroll
    for (int i = 0; i < TM; i++)
#pragma unroll
        for (int p = 0; p < TNP; p++) acc[i][p] = 0ull;

#pragma unroll 4
    for (int k = 0; k < 128; ++k) {
        unsigned long long w[TNP];
#pragma unroll
        for (int p = 0; p < TNP; p++)
            w[p] = *reinterpret_cast<const unsigned long long*>(
                Wsh + k * NOUT + colbase + 2 * p);
#pragma unroll
        for (int i = 0; i < TM; i++) {
            unsigned long long aa = pack2(arow[i * ASTR + k]);
#pragma unroll
            for (int p = 0; p < TNP; p++) ffma2(acc[i][p], aa, w[p]);
        }
    }

#pragma unroll
    for (int i = 0; i < TM; i++) {
        int gr = row0 + rt * TM + i;
        if (gr < M) {
            float* o = out + (size_t)gr * NOUT + colbase;
#pragma unroll
            for (int p = 0; p < TNP; p += 2) {
                U2F2 u0, u1;
                u0.u = acc[i][p];
                u1.u = acc[i][p + 1];
                *reinterpret_cast<float4*>(o + 2 * p) =
                    make_float4(u0.f.x, u0.f.y, u1.f.x, u1.f.y);
            }
        }
    }
}

// ---------------------------------------------------------------------------
// Fused CSR aggregate + combine — 8-way MLP
// ---------------------------------------------------------------------------
#define ACC4(d, v) { d.x += v.x; d.y += v.y; d.z += v.z; d.w += v.w; }

template <bool RELU>
__global__ void aggcomb128(const float* __restrict__ TS,
                           const float* __restrict__ b,
                           float* __restrict__ out, int M) {
    int n = blockIdx.x * 8 + (threadIdx.x >> 5);
    if (n >= M) return;
    int lane = threadIdx.x & 31;
    int beg = g_off[n], end = g_off[n + 1];

    float4 a0 = make_float4(0.f, 0.f, 0.f, 0.f);
    float4 a1 = make_float4(0.f, 0.f, 0.f, 0.f);
    float4 a2 = make_float4(0.f, 0.f, 0.f, 0.f);
    float4 a3 = make_float4(0.f, 0.f, 0.f, 0.f);

    for (int j0 = beg; j0 < end; j0 += 32) {
        int cnt = min(32, end - j0);
        int s = (lane < cnt) ? g_esrc[j0 + lane] : 0;
        int t = 0;
        for (; t + 7 < cnt; t += 8) {
            int s0 = __shfl_sync(0xffffffffu, s, t);
            int s1 = __shfl_sync(0xffffffffu, s, t + 1);
            int s2 = __shfl_sync(0xffffffffu, s, t + 2);
            int s3 = __shfl_sync(0xffffffffu, s, t + 3);
            int s4 = __shfl_sync(0xffffffffu, s, t + 4);
            int s5 = __shfl_sync(0xffffffffu, s, t + 5);
            int s6 = __shfl_sync(0xffffffffu, s, t + 6);
            int s7 = __shfl_sync(0xffffffffu, s, t + 7);
            float4 v0 = *reinterpret_cast<const float4*>(TS + (size_t)s0 * 256 + lane * 4);
            float4 v1 = *reinterpret_cast<const float4*>(TS + (size_t)s1 * 256 + lane * 4);
            float4 v2 = *reinterpret_cast<const float4*>(TS + (size_t)s2 * 256 + lane * 4);
            float4 v3 = *reinterpret_cast<const float4*>(TS + (size_t)s3 * 256 + lane * 4);
            float4 v4 = *reinterpret_cast<const float4*>(TS + (size_t)s4 * 256 + lane * 4);
            float4 v5 = *reinterpret_cast<const float4*>(TS + (size_t)s5 * 256 + lane * 4);
            float4 v6 = *reinterpret_cast<const float4*>(TS + (size_t)s6 * 256 + lane * 4);
            float4 v7 = *reinterpret_cast<const float4*>(TS + (size_t)s7 * 256 + lane * 4);
            ACC4(a0, v0) ACC4(a1, v1) ACC4(a2, v2) ACC4(a3, v3)
            ACC4(a0, v4) ACC4(a1, v5) ACC4(a2, v6) ACC4(a3, v7)
        }
        for (; t + 3 < cnt; t += 4) {
            int s0 = __shfl_sync(0xffffffffu, s, t);
            int s1 = __shfl_sync(0xffffffffu, s, t + 1);
            int s2 = __shfl_sync(0xffffffffu, s, t + 2);
            int s3 = __shfl_sync(0xffffffffu, s, t + 3);
            float4 v0 = *reinterpret_cast<const float4*>(TS + (size_t)s0 * 256 + lane * 4);
            float4 v1 = *reinterpret_cast<const float4*>(TS + (size_t)s1 * 256 + lane * 4);
            float4 v2 = *reinterpret_cast<const float4*>(TS + (size_t)s2 * 256 + lane * 4);
            float4 v3 = *reinterpret_cast<const float4*>(TS + (size_t)s3 * 256 + lane * 4);
            ACC4(a0, v0) ACC4(a1, v1) ACC4(a2, v2) ACC4(a3, v3)
        }
        for (; t < cnt; ++t) {
            int s0 = __shfl_sync(0xffffffffu, s, t);
            float4 v0 = *reinterpret_cast<const float4*>(TS + (size_t)s0 * 256 + lane * 4);
            ACC4(a0, v0)
        }
    }
    float r = g_rdeg[n];
    float4 sf = *reinterpret_cast<const float4*>(TS + (size_t)n * 256 + 128 + lane * 4);
    float4 bb = *reinterpret_cast<const float4*>(b + lane * 4);
    float4 v;
    v.x = sf.x + (a0.x + a1.x + a2.x + a3.x) * r + bb.x;
    v.y = sf.y + (a0.y + a1.y + a2.y + a3.y) * r + bb.y;
    v.z = sf.z + (a0.z + a1.z + a2.z + a3.z) * r + bb.z;
    v.w = sf.w + (a0.w + a1.w + a2.w + a3.w) * r + bb.w;
    if (RELU) {
        v.x = fmaxf(v.x, 0.f); v.y = fmaxf(v.y, 0.f);
        v.z = fmaxf(v.z, 0.f); v.w = fmaxf(v.w, 0.f);
    }
    *reinterpret_cast<float4*>(out + (size_t)n * 128 + lane * 4) = v;
}

__global__ void aggcomb40(const float* __restrict__ TS,
                          const float* __restrict__ b,
                          float* __restrict__ out, int M) {
    int n = blockIdx.x * 8 + (threadIdx.x >> 5);
    if (n >= M) return;
    int lane = threadIdx.x & 31;
    int beg = g_off[n], end = g_off[n + 1];
    bool act = lane < 10;
    int laneo = act ? lane : 0;

    float4 a0 = make_float4(0.f, 0.f, 0.f, 0.f);
    float4 a1 = make_float4(0.f, 0.f, 0.f, 0.f);
    float4 a2 = make_float4(0.f, 0.f, 0.f, 0.f);
    float4 a3 = make_float4(0.f, 0.f, 0.f, 0.f);

    for (int j0 = beg; j0 < end; j0 += 32) {
        int cnt = min(32, end - j0);
        int s = (lane < cnt) ? g_esrc[j0 + lane] : 0;
        int t = 0;
        for (; t + 7 < cnt; t += 8) {
            int s0 = __shfl_sync(0xffffffffu, s, t);
            int s1 = __shfl_sync(0xffffffffu, s, t + 1);
            int s2 = __shfl_sync(0xffffffffu, s, t + 2);
            int s3 = __shfl_sync(0xffffffffu, s, t + 3);
            int s4 = __shfl_sync(0xffffffffu, s, t + 4);
            int s5 = __shfl_sync(0xffffffffu, s, t + 5);
            int s6 = __shfl_sync(0xffffffffu, s, t + 6);
            int s7 = __shfl_sync(0xffffffffu, s, t + 7);
            float4 v0 = *reinterpret_cast<const float4*>(TS + (size_t)s0 * 80 + laneo * 4);
            float4 v1 = *reinterpret_cast<const float4*>(TS + (size_t)s1 * 80 + laneo * 4);
            float4 v2 = *reinterpret_cast<const float4*>(TS + (size_t)s2 * 80 + laneo * 4);
            float4 v3 = *reinterpret_cast<const float4*>(TS + (size_t)s3 * 80 + laneo * 4);
            float4 v4 = *reinterpret_cast<const float4*>(TS + (size_t)s4 * 80 + laneo * 4);
            float4 v5 = *reinterpret_cast<const float4*>(TS + (size_t)s5 * 80 + laneo * 4);
            float4 v6 = *reinterpret_cast<const float4*>(TS + (size_t)s6 * 80 + laneo * 4);
            float4 v7 = *reinterpret_cast<const float4*>(TS + (size_t)s7 * 80 + laneo * 4);
            ACC4(a0, v0) ACC4(a1, v1) ACC4(a2, v2) ACC4(a3, v3)
            ACC4(a0, v4) ACC4(a1, v5) ACC4(a2, v6) ACC4(a3, v7)
        }
        for (; t + 3 < cnt; t += 4) {
            int s0 = __shfl_sync(0xffffffffu, s, t);
            int s1 = __shfl_sync(0xffffffffu, s, t + 1);
            int s2 = __shfl_sync(0xffffffffu, s, t + 2);
            int s3 = __shfl_sync(0xffffffffu, s, t + 3);
            float4 v0 = *reinterpret_cast<const float4*>(TS + (size_t)s0 * 80 + laneo * 4);
            float4 v1 = *reinterpret_cast<const float4*>(TS + (size_t)s1 * 80 + laneo * 4);
            float4 v2 = *reinterpret_cast<const float4*>(TS + (size_t)s2 * 80 + laneo * 4);
            float4 v3 = *reinterpret_cast<const float4*>(TS + (size_t)s3 * 80 + laneo * 4);
            ACC4(a0, v0) ACC4(a1, v1) ACC4(a2, v2) ACC4(a3, v3)
        }
        for (; t < cnt; ++t) {
            int s0 = __shfl_sync(0xffffffffu, s, t);
            float4 v0 = *reinterpret_cast<const float4*>(TS + (size_t)s0 * 80 + laneo * 4);
            ACC4(a0, v0)
        }
    }
    if (act) {
        float r = g_rdeg[n];
        float4 sf = *reinterpret_cast<const float4*>(TS + (size_t)n * 80 + 40 + lane * 4);
        float4 bb = *reinterpret_cast<const float4*>(b + lane * 4);
        float4 v;
        v.x = sf.x + (a0.x + a1.x + a2.x + a3.x) * r + bb.x;
        v.y = sf.y + (a0.y + a1.y + a2.y + a3.y) * r + bb.y;
        v.z = sf.z + (a0.z + a1.z + a2.z + a3.z) * r + bb.z;
        v.w = sf.w + (a0.w + a1.w + a2.w + a3.w) * r + bb.w;
        *reinterpret_cast<float4*>(out + (size_t)n * 40 + lane * 4) = v;
    }
}

// ---------------------------------------------------------------------------
// launch
// ---------------------------------------------------------------------------
static inline int cdiv(int a, int b) { return (a + b - 1) / b; }

extern "C" void kernel_launch(void* const* d_in, const int* in_sizes, int n_in,
                              void* d_out, int out_size) {
    const float* feat = (const float*)d_in[0];
    const int*   src  = (const int*)d_in[1];
    const int*   dst  = (const int*)d_in[2];
    const float* wS0 = (const float*)d_in[3];
    const float* wN0 = (const float*)d_in[4];
    const float* b0  = (const float*)d_in[5];
    const float* wS1 = (const float*)d_in[6];
    const float* wN1 = (const float*)d_in[7];
    const float* b1  = (const float*)d_in[8];
    const float* wS2 = (const float*)d_in[9];
    const float* wN2 = (const float*)d_in[10];
    const float* b2  = (const float*)d_in[11];
    float* out = (float*)d_out;

    const int M = in_sizes[0] / 128;
    const int E = in_sizes[1];

    void *pTS, *pH, *pDegi, *pOff, *pBsum, *pBh, *pBl;
    cudaGetSymbolAddress(&pTS, g_TS);
    cudaGetSymbolAddress(&pH, g_H);
    cudaGetSymbolAddress(&pDegi, g_degi);
    cudaGetSymbolAddress(&pOff, g_off);
    cudaGetSymbolAddress(&pBsum, g_bsum);
    cudaGetSymbolAddress(&pBh, g_Bh);
    cudaGetSymbolAddress(&pBl, g_Bl);
    float* TS = (float*)pTS;
    float* H = (float*)pH;
    int* degi = (int*)pDegi;
    int* off = (int*)pOff;
    int* bsum = (int*)pBsum;
    unsigned short* Bh = (unsigned short*)pBh;
    unsigned short* Bl = (unsigned short*)pBl;

    constexpr int SMEM_B = (128 * 80 + 128 * 132) * 4;   // 108544 B
    static bool attr_done = false;
    if (!attr_done) {
        cudaFuncSetAttribute((const void*)gemm128_mma,
                             cudaFuncAttributeMaxDynamicSharedMemorySize, SMEM_MMA);
        cudaFuncSetAttribute((const void*)gemm_fused<40, 10, 32, 4, 4>,
                             cudaFuncAttributeMaxDynamicSharedMemorySize, SMEM_B);
        attr_done = true;
    }

    const int gemm_blocks = cdiv(M, 128);
    const int nscan = cdiv(M, 256);
    const int node_blocks = cdiv(M, 8);
    const int e4_blocks = cdiv(cdiv(E, 4), 256);

    // launch #4 = gemm128_mma (profiler captures it)
    w_prep<<<64, 256>>>(wN0, wS0, Bh + 0 * 32768, Bl + 0 * 32768);   // 1
    w_prep<<<64, 256>>>(wN1, wS1, Bh + 1 * 32768, Bl + 1 * 32768);   // 2
    zero_i<<<cdiv(M, 256), 256>>>(degi, M);                          // 3
    gemm128_mma<<<gemm_blocks, 512, SMEM_MMA>>>(feat, Bh, Bl, TS, M); // 4 (layer1 GEMM)

    // CSR build (independent of TS)
    count_deg4<<<e4_blocks, 256>>>(dst, E);                          // 5
    scan_block<<<nscan, 256>>>(degi, off, bsum, M);                  // 6
    scan_block<<<1, 256>>>(bsum, bsum, nullptr, nscan);              // 7
    add_off<<<cdiv(M + 1, 256), 256>>>(M, E);                        // 8 (+cur,+rdeg)
    scatter_edges4<<<e4_blocks, 256>>>(src, dst, E);                 // 9

    // layer 1 aggregate
    aggcomb128<true><<<node_blocks, 256>>>(TS, b0, H, M);            // 10

    // layer 2
    gemm128_mma<<<gemm_blocks, 512, SMEM_MMA>>>(H, Bh + 32768, Bl + 32768, TS, M);
    aggcomb128<true><<<node_blocks, 256>>>(TS, b1, H, M);

    // layer 3
    gemm_fused<40, 10, 32, 4, 4><<<gemm_blocks, 320, SMEM_B>>>(H, wN2, wS2, TS, M);
    aggcomb40<<<node_blocks, 256>>>(TS, b2, out, M);
}